// round 13
// baseline (speedup 1.0000x reference)
#include <cuda_runtime.h>
#include <cuda_bf16.h>
#include <cstdint>

// Problem constants (fixed shapes)
#define NB   2
#define NT   16
#define NN   10000
#define NIN  128
#define NHID 256
#define NOUT 128
#define NE   160000

#define ROWS (NB*NN)          // 20000
#define HISTROWS (NB*NT*NN)   // 320000
#define KCAT 384              // 128 (x-agg) + 256 (h-agg)
#define GC   1024             // interleaved: col 4*d+gate, gate = r,z,xn,hn

// GEMM tiles: 128 threads = 4 warps (2 M x 2 N), warp tile 64x32
#define BM 128
#define BN 64
#define BK 16
#define STAGE_BYTES 12288u    // Ahi4K|Alo4K|Bhi2K|Blo2K

typedef __nv_bfloat16 bf16;

// ---------------- device scratch (static, no allocations) ----------------
__device__ bf16  g_AxHi[(size_t)HISTROWS * NIN];    // 82 MB  (A*x_t, all t)
__device__ bf16  g_AxLo[(size_t)HISTROWS * NIN];
__device__ bf16  g_AhHi[(size_t)ROWS * NHID];       // 10.2 MB (A*h, current step)
__device__ bf16  g_AhLo[(size_t)ROWS * NHID];
__device__ float g_h[(size_t)ROWS * NHID];          // 20.5 MB (fp32 h state)
__device__ bf16  g_histHi[(size_t)HISTROWS * NHID]; // 164 MB (h_t splits, all t)
__device__ bf16  g_histLo[(size_t)HISTROWS * NHID];
__device__ bf16  g_WThi[GC * KCAT];                 // [n'][k] transposed
__device__ bf16  g_WTlo[GC * KCAT];
__device__ bf16  g_WfcThi[NOUT * NHID];             // [o][k]
__device__ bf16  g_WfcTlo[NOUT * NHID];
__device__ float g_biasPack[GC];                    // interleaved 4*d+gate
__device__ int   g_rowptr[NN + 1];
__device__ int   g_counts[NN];
__device__ int   g_fill[NN];
__device__ float g_dinv[NN];
__device__ int   g_col[NE];
__device__ float g_wedge[NE];

__device__ __forceinline__ void split2(float v, bf16& hi, bf16& lo) {
    hi = __float2bfloat16_rn(v);
    lo = __float2bfloat16_rn(v - __bfloat162float(hi));
}

// ---------------- setup kernels ----------------
__global__ void k_zero_all() {
    for (int i = blockIdx.x * blockDim.x + threadIdx.x;
         i < ROWS * NHID; i += gridDim.x * blockDim.x) {
        if (i < NN) g_counts[i] = 0;
        g_h[i] = 0.0f;
    }
}

__global__ void k_count(const int* __restrict__ ei) {
    int e = blockIdx.x * blockDim.x + threadIdx.x;
    if (e < NE) atomicAdd(&g_counts[ei[NE + e]], 1);   // dst row
}

// single block: dinv + exclusive scan + fill init + CSR scatter
__global__ void k_scan_all(const int* __restrict__ ei) {
    __shared__ int ssum[1024];
    int tid = threadIdx.x;
    const int CH = (NN + 1023) / 1024;   // 10
    int start = tid * CH;
    int s = 0;
    for (int i = 0; i < CH; i++) {
        int idx = start + i;
        if (idx < NN) s += g_counts[idx];
    }
    ssum[tid] = s;
    __syncthreads();
    for (int off = 1; off < 1024; off <<= 1) {
        int v = 0;
        if (tid >= off) v = ssum[tid - off];
        __syncthreads();
        ssum[tid] += v;
        __syncthreads();
    }
    int run = ssum[tid] - s;   // exclusive prefix
    for (int i = 0; i < CH; i++) {
        int idx = start + i;
        if (idx < NN) {
            g_rowptr[idx] = run;
            g_fill[idx]   = run;
            g_dinv[idx]   = rsqrtf((float)g_counts[idx] + 1.0f);
            run += g_counts[idx];
        }
    }
    if (tid == 1023) g_rowptr[NN] = ssum[1023];
    __syncthreads();
    for (int e = tid; e < NE; e += 1024) {
        int sc = ei[e];
        int d  = ei[NE + e];
        int pos = atomicAdd(&g_fill[d], 1);
        g_col[pos]   = sc;
        g_wedge[pos] = g_dinv[sc] * g_dinv[d];
    }
}

// ---------------- agg(x_t) for ALL t in one launch ----------------
__global__ void k_aggx(const float* __restrict__ x) {
    int node = blockIdx.x;
    int bt = blockIdx.y * 4 + threadIdx.y;   // 0..31, = t*NB + b
    int t = bt >> 1, b = bt & 1;
    int tx = threadIdx.x;                    // feature/4
    const float* vi = x + ((size_t)(b * NT + t) * NN) * NIN;
    float di = g_dinv[node];
    float4 acc = *(const float4*)(vi + (size_t)node * NIN + tx * 4);
    float sw = di * di;
    acc.x *= sw; acc.y *= sw; acc.z *= sw; acc.w *= sw;
    int beg = g_rowptr[node], end = g_rowptr[node + 1];
    int j = beg;
    for (; j + 1 < end; j += 2) {
        float w0 = g_wedge[j],     w1 = g_wedge[j + 1];
        int   c0 = g_col[j],       c1 = g_col[j + 1];
        float4 v0 = *(const float4*)(vi + (size_t)c0 * NIN + tx * 4);
        float4 v1 = *(const float4*)(vi + (size_t)c1 * NIN + tx * 4);
        acc.x += w0 * v0.x + w1 * v1.x; acc.y += w0 * v0.y + w1 * v1.y;
        acc.z += w0 * v0.z + w1 * v1.z; acc.w += w0 * v0.w + w1 * v1.w;
    }
    if (j < end) {
        float w = g_wedge[j]; int c = g_col[j];
        float4 v = *(const float4*)(vi + (size_t)c * NIN + tx * 4);
        acc.x += w * v.x; acc.y += w * v.y; acc.z += w * v.z; acc.w += w * v.w;
    }
    size_t o = ((size_t)bt * NN + node) * NIN + tx * 4;  // = (t*ROWS + b*NN + node)*NIN
    bf16 h0, l0, h1, l1, h2, l2, h3, l3;
    split2(acc.x, h0, l0); split2(acc.y, h1, l1);
    split2(acc.z, h2, l2); split2(acc.w, h3, l3);
    *(ushort4*)(g_AxHi + o) = make_ushort4(__bfloat16_as_ushort(h0), __bfloat16_as_ushort(h1),
                                           __bfloat16_as_ushort(h2), __bfloat16_as_ushort(h3));
    *(ushort4*)(g_AxLo + o) = make_ushort4(__bfloat16_as_ushort(l0), __bfloat16_as_ushort(l1),
                                           __bfloat16_as_ushort(l2), __bfloat16_as_ushort(l3));
}

// ---------------- agg(h) per step ----------------
__global__ void k_aggh() {
    int node = blockIdx.x;
    int b    = threadIdx.y;
    int tx   = threadIdx.x;          // 0..63
    const float* vi = g_h + (size_t)b * NN * NHID;
    float di = g_dinv[node];
    float4 acc = *(const float4*)(vi + (size_t)node * NHID + tx * 4);
    float sw = di * di;
    acc.x *= sw; acc.y *= sw; acc.z *= sw; acc.w *= sw;
    int beg = g_rowptr[node], end = g_rowptr[node + 1];
    int j = beg;
    for (; j + 1 < end; j += 2) {
        float w0 = g_wedge[j],     w1 = g_wedge[j + 1];
        int   c0 = g_col[j],       c1 = g_col[j + 1];
        float4 v0 = *(const float4*)(vi + (size_t)c0 * NHID + tx * 4);
        float4 v1 = *(const float4*)(vi + (size_t)c1 * NHID + tx * 4);
        acc.x += w0 * v0.x + w1 * v1.x; acc.y += w0 * v0.y + w1 * v1.y;
        acc.z += w0 * v0.z + w1 * v1.z; acc.w += w0 * v0.w + w1 * v1.w;
    }
    if (j < end) {
        float w = g_wedge[j]; int c = g_col[j];
        float4 v = *(const float4*)(vi + (size_t)c * NHID + tx * 4);
        acc.x += w * v.x; acc.y += w * v.y; acc.z += w * v.z; acc.w += w * v.w;
    }
    size_t o = ((size_t)b * NN + node) * NHID + tx * 4;
    bf16 h0, l0, h1, l1, h2, l2, h3, l3;
    split2(acc.x, h0, l0); split2(acc.y, h1, l1);
    split2(acc.z, h2, l2); split2(acc.w, h3, l3);
    *(ushort4*)(g_AhHi + o) = make_ushort4(__bfloat16_as_ushort(h0), __bfloat16_as_ushort(h1),
                                           __bfloat16_as_ushort(h2), __bfloat16_as_ushort(h3));
    *(ushort4*)(g_AhLo + o) = make_ushort4(__bfloat16_as_ushort(l0), __bfloat16_as_ushort(l1),
                                           __bfloat16_as_ushort(l2), __bfloat16_as_ushort(l3));
}

// ---------------- weight packing (transposed + gate-interleaved + split) ----
__global__ void k_pack(const float* __restrict__ Wxr, const float* __restrict__ Whr,
                       const float* __restrict__ Wxz, const float* __restrict__ Whz,
                       const float* __restrict__ Wxn, const float* __restrict__ Whn,
                       const float* __restrict__ bxr, const float* __restrict__ bhr,
                       const float* __restrict__ bxz, const float* __restrict__ bhz,
                       const float* __restrict__ bxn, const float* __restrict__ bhn,
                       const float* __restrict__ Wfc) {
    int idx = blockIdx.x * blockDim.x + threadIdx.x;
    if (idx < GC * KCAT) {
        int cp = idx / KCAT;
        int k  = idx - cp * KCAT;
        int d = cp >> 2, g = cp & 3;
        bool xk = k < 128;
        int kh = k - 128;
        float v;
        if (g == 0)      v = xk ? Wxr[k * 256 + d] : Whr[kh * 256 + d];
        else if (g == 1) v = xk ? Wxz[k * 256 + d] : Whz[kh * 256 + d];
        else if (g == 2) v = xk ? Wxn[k * 256 + d] : 0.0f;
        else             v = xk ? 0.0f : Whn[kh * 256 + d];
        bf16 hi, lo; split2(v, hi, lo);
        g_WThi[idx] = hi; g_WTlo[idx] = lo;
    }
    if (idx < GC) {
        int d = idx >> 2, g = idx & 3;
        float bv;
        if (g == 0)      bv = bxr[d] + bhr[d];
        else if (g == 1) bv = bxz[d] + bhz[d];
        else if (g == 2) bv = bxn[d];
        else             bv = bhn[d];
        g_biasPack[idx] = bv;
    }
    if (idx < NOUT * NHID) {
        int o = idx >> 8;          // NHID = 256
        int k = idx & 255;
        bf16 hi, lo; split2(Wfc[k * NOUT + o], hi, lo);
        g_WfcThi[idx] = hi; g_WfcTlo[idx] = lo;
    }
}

// ---------------- split-bf16 mma.sync GEMM (128 threads, 3 CTAs/SM) ------
// GATES=true: A = [Ax(t) | Ah], K=384 (128 at t=0); fused GRU epilogue
//             updating g_h + writing h splits into hist[t].
// GATES=false: A = hist (M=320000, K=256); bias + scatter into out[B,T,N,OUT].

__device__ __forceinline__ uint32_t smem_u32(const void* p) {
    uint32_t a;
    asm("{ .reg .u64 t; cvta.to.shared.u64 t, %1; cvt.u32.u64 %0, t; }"
        : "=r"(a) : "l"(p));
    return a;
}

__device__ __forceinline__ void ldsm4(uint32_t& r0, uint32_t& r1, uint32_t& r2,
                                      uint32_t& r3, uint32_t addr) {
    asm volatile("ldmatrix.sync.aligned.m8n8.x4.shared.b16 {%0,%1,%2,%3}, [%4];"
                 : "=r"(r0), "=r"(r1), "=r"(r2), "=r"(r3) : "r"(addr));
}

__device__ __forceinline__ void mma16(float* c, const uint32_t* a, const uint32_t* b) {
    asm volatile(
        "mma.sync.aligned.m16n8k16.row.col.f32.bf16.bf16.f32 "
        "{%0,%1,%2,%3}, {%4,%5,%6,%7}, {%8,%9}, {%0,%1,%2,%3};"
        : "+f"(c[0]), "+f"(c[1]), "+f"(c[2]), "+f"(c[3])
        : "r"(a[0]), "r"(a[1]), "r"(a[2]), "r"(a[3]), "r"(b[0]), "r"(b[1]));
}

template <bool GATES>
__global__ void __launch_bounds__(128)
k_mma(const bf16* __restrict__ A0hi, const bf16* __restrict__ A0lo,
      const bf16* __restrict__ A1hi, const bf16* __restrict__ A1lo,
      const bf16* __restrict__ Bhi, const bf16* __restrict__ Blo, int ldb,
      float* __restrict__ C, const float* __restrict__ bias,
      int M, int K, int t) {
    // 3 stages x 12KB: [Ahi 4K: kh*2048+row*16][Alo 4K][Bhi 2K: kh*1024+row*16][Blo 2K]
    __shared__ __align__(16) char smem[3 * STAGE_BYTES];

    const int tid = threadIdx.x;
    const int lane = tid & 31;
    const int wid = tid >> 5;
    const int wm = wid & 1;          // 2 warps in M (64 rows each)
    const int wn = wid >> 1;         // 2 warps in N (32 cols each)
    const int m0 = blockIdx.y * BM;
    const int n0 = blockIdx.x * BN;

    const uint32_t sbase = smem_u32(smem);

    // staging: A row = tid (128 rows, both khalfs); B row = tid&63, kh = tid>>6
    const int a_row = tid;
    const int b_row = tid & 63;
    const int b_kh  = tid >> 6;

    const int r = m0 + a_row;
    const bool rvalid = r < M;
    const int rc = rvalid ? r : 0;
    const bf16 *aXhi, *aXlo, *aHhi, *aHlo;
    if (GATES) {
        size_t xoff = ((size_t)t * ROWS + rc) * NIN;
        aXhi = A0hi + xoff; aXlo = A0lo + xoff;
        size_t hoff = (size_t)rc * NHID;
        aHhi = A1hi + hoff; aHlo = A1lo + hoff;
    } else {
        size_t off = (size_t)rc * NHID;
        aXhi = A0hi + off; aXlo = A0lo + off;
        aHhi = A0hi; aHlo = A0lo;   // unused
    }
    const bf16* bSrcHi = Bhi + (size_t)(n0 + b_row) * ldb + b_kh * 8;
    const bf16* bSrcLo = Blo + (size_t)(n0 + b_row) * ldb + b_kh * 8;
    const int pa = rvalid ? 16 : 0;

    // ldmatrix lane geometry
    const int lrow = lane & 15;
    const int lkh  = lane >> 4;

    float acc[4][4][4];
#pragma unroll
    for (int i = 0; i < 4; i++)
#pragma unroll
        for (int j = 0; j < 4; j++)
#pragma unroll
            for (int q = 0; q < 4; q++) acc[i][j][q] = 0.0f;

    const int KT = K / BK;

    auto stage = [&](int buf, int k0) {
        uint32_t base = sbase + (uint32_t)buf * STAGE_BYTES;
        const bf16 *sa_hi, *sa_lo;
        if (GATES && k0 >= NIN) { sa_hi = aHhi + (k0 - NIN); sa_lo = aHlo + (k0 - NIN); }
        else                    { sa_hi = aXhi + k0;         sa_lo = aXlo + k0; }
#pragma unroll
        for (int kh = 0; kh < 2; kh++) {
            uint32_t o = (uint32_t)(kh * 2048 + a_row * 16);
            asm volatile("cp.async.ca.shared.global [%0], [%1], 16, %2;"
                         :: "r"(base + o), "l"(sa_hi + kh * 8), "r"(pa));
            asm volatile("cp.async.ca.shared.global [%0], [%1], 16, %2;"
                         :: "r"(base + 4096u + o), "l"(sa_lo + kh * 8), "r"(pa));
        }
        uint32_t bo = (uint32_t)(b_kh * 1024 + b_row * 16);
        asm volatile("cp.async.ca.shared.global [%0], [%1], 16, %2;"
                     :: "r"(base + 8192u + bo), "l"(bSrcHi + k0), "r"(16));
        asm volatile("cp.async.ca.shared.global [%0], [%1], 16, %2;"
                     :: "r"(base + 10240u + bo), "l"(bSrcLo + k0), "r"(16));
    };

    stage(0, 0);
    asm volatile("cp.async.commit_group;");
    stage(1, BK);
    asm volatile("cp.async.commit_group;");

    for (int kt = 0; kt < KT; kt++) {
        if (kt + 2 < KT) {
            stage((kt + 2) % 3, (kt + 2) * BK);
            asm volatile("cp.async.commit_group;");
            asm volatile("cp.async.wait_group 2;");
        } else if (kt + 1 < KT) {
            asm volatile("cp.async.wait_group 1;");
        } else {
            asm volatile("cp.async.wait_group 0;");
        }
        __syncthreads();

        const uint32_t pA  = sbase + (uint32_t)(kt % 3) * STAGE_BYTES;
        const uint32_t pA2 = pA + 4096u;
        const uint32_t pB  = pA + 8192u;
        const uint32_t pB2 = pA + 10240u;
        const uint32_t loffA = (uint32_t)(lkh * 2048);
        const uint32_t loffB = (uint32_t)(lkh * 1024);

        uint32_t ah[4][4], al[4][4], bh[4][2], bl[4][2];
#pragma unroll
        for (int mt = 0; mt < 4; mt++) {
            uint32_t ro = (uint32_t)((wm * 64 + mt * 16 + lrow) * 16);
            ldsm4(ah[mt][0], ah[mt][1], ah[mt][2], ah[mt][3], pA + loffA + ro);
            ldsm4(al[mt][0], al[mt][1], al[mt][2], al[mt][3], pA2 + loffA + ro);
        }
#pragma unroll
        for (int j = 0; j < 2; j++) {
            uint32_t ro = (uint32_t)((wn * 32 + j * 16 + lrow) * 16);
            uint32_t r0, r1, r2, r3;
            ldsm4(r0, r1, r2, r3, pB + loffB + ro);
            bh[2*j][0] = r0; bh[2*j][1] = r2;
            bh[2*j+1][0] = r1; bh[2*j+1][1] = r3;
            ldsm4(r0, r1, r2, r3, pB2 + loffB + ro);
            bl[2*j][0] = r0; bl[2*j][1] = r2;
            bl[2*j+1][0] = r1; bl[2*j+1][1] = r3;
        }
#pragma unroll
        for (int mt = 0; mt < 4; mt++)
#pragma unroll
            for (int nt = 0; nt < 4; nt++) {
                mma16(acc[mt][nt], ah[mt], bh[nt]);
                mma16(acc[mt][nt], ah[mt], bl[nt]);
                mma16(acc[mt][nt], al[mt], bh[nt]);
            }
        __syncthreads();
    }

    // ---- epilogue ----
    const int gid = lane >> 2, tg = lane & 3;

    if (GATES) {
        const bool odd = lane & 1;
#pragma unroll
        for (int mt = 0; mt < 4; mt++) {
            int rowb = m0 + wm * 64 + mt * 16;
#pragma unroll
            for (int nt = 0; nt < 4; nt++) {
                float c0 = acc[mt][nt][0], c1 = acc[mt][nt][1];
                float c2 = acc[mt][nt][2], c3 = acc[mt][nt][3];
                float e0 = __shfl_xor_sync(0xffffffffu, c0, 1);
                float e1 = __shfl_xor_sync(0xffffffffu, c1, 1);
                float e2 = __shfl_xor_sync(0xffffffffu, c2, 1);
                float e3 = __shfl_xor_sync(0xffffffffu, c3, 1);
                float v0, v1, v2, v3;
                int row;
                if (!odd) { v0 = c0; v1 = c1; v2 = e0; v3 = e1; row = rowb + gid; }
                else      { v0 = e2; v1 = e3; v2 = c2; v3 = c3; row = rowb + gid + 8; }
                int d = ((n0 + wn * 32 + nt * 8) >> 2) + (tg >> 1);
                if (row < M) {
                    float4 bb = *(const float4*)&bias[4 * d];
                    float rg = 1.0f / (1.0f + __expf(-(v0 + bb.x)));
                    float zg = 1.0f / (1.0f + __expf(-(v1 + bb.y)));
                    float ng = tanhf(v2 + bb.z + rg * (v3 + bb.w));
                    size_t hoff = (size_t)row * NHID + d;
                    float h = g_h[hoff];
                    float hn2 = h + zg * (ng - h);
                    g_h[hoff] = hn2;
                    bf16 hi, lo; split2(hn2, hi, lo);
                    size_t hist = ((size_t)t * ROWS + row) * NHID + d;
                    g_histHi[hist] = hi;
                    g_histLo[hist] = lo;
                }
            }
        }
    } else {
#pragma unroll
        for (int mt = 0; mt < 4; mt++) {
            int r0 = m0 + wm * 64 + mt * 16 + gid;
            int r1 = r0 + 8;
            // r = t*ROWS + b*NN + node -> out[((b*NT+t)*NN+node)*NOUT]
            int t0 = r0 / ROWS, rm0 = r0 - t0 * ROWS;
            int b0 = rm0 / NN,  nd0 = rm0 - b0 * NN;
            int t1 = r1 / ROWS, rm1 = r1 - t1 * ROWS;
            int b1 = rm1 / NN,  nd1 = rm1 - b1 * NN;
            size_t base0 = (((size_t)b0 * NT + t0) * NN + nd0) * NOUT;
            size_t base1 = (((size_t)b1 * NT + t1) * NN + nd1) * NOUT;
#pragma unroll
            for (int nt = 0; nt < 4; nt++) {
                int col = n0 + wn * 32 + nt * 8 + tg * 2;
                float bx = bias[col], by = bias[col + 1];
                float2 o0 = make_float2(acc[mt][nt][0] + bx, acc[mt][nt][1] + by);
                *(float2*)&C[base0 + col] = o0;
                float2 o1 = make_float2(acc[mt][nt][2] + bx, acc[mt][nt][3] + by);
                *(float2*)&C[base1 + col] = o1;
            }
        }
    }
}

// ---------------- launcher ----------------
extern "C" void kernel_launch(void* const* d_in, const int* in_sizes, int n_in,
                              void* d_out, int out_size) {
    (void)in_sizes; (void)n_in; (void)out_size;
    const float* x   = (const float*)d_in[0];
    const int*   ei  = (const int*)d_in[1];
    const float* Wxr = (const float*)d_in[2];  const float* bxr = (const float*)d_in[3];
    const float* Whr = (const float*)d_in[4];  const float* bhr = (const float*)d_in[5];
    const float* Wxz = (const float*)d_in[6];  const float* bxz = (const float*)d_in[7];
    const float* Whz = (const float*)d_in[8];  const float* bhz = (const float*)d_in[9];
    const float* Wxn = (const float*)d_in[10]; const float* bxn = (const float*)d_in[11];
    const float* Whn = (const float*)d_in[12]; const float* bhn = (const float*)d_in[13];
    const float* Wfc = (const float*)d_in[14]; const float* bfc = (const float*)d_in[15];
    float* out = (float*)d_out;

    bf16 *pAxHi, *pAxLo, *pAhHi, *pAhLo, *pHistHi, *pHistLo;
    bf16 *pWThi, *pWTlo, *pWfcThi, *pWfcTlo;
    float *pbias;
    cudaGetSymbolAddress((void**)&pAxHi,   g_AxHi);
    cudaGetSymbolAddress((void**)&pAxLo,   g_AxLo);
    cudaGetSymbolAddress((void**)&pAhHi,   g_AhHi);
    cudaGetSymbolAddress((void**)&pAhLo,   g_AhLo);
    cudaGetSymbolAddress((void**)&pHistHi, g_histHi);
    cudaGetSymbolAddress((void**)&pHistLo, g_histLo);
    cudaGetSymbolAddress((void**)&pWThi,   g_WThi);
    cudaGetSymbolAddress((void**)&pWTlo,   g_WTlo);
    cudaGetSymbolAddress((void**)&pWfcThi, g_WfcThi);
    cudaGetSymbolAddress((void**)&pWfcTlo, g_WfcTlo);
    cudaGetSymbolAddress((void**)&pbias,   g_biasPack);

    // setup
    k_zero_all<<<592, 256>>>();
    k_count<<<(NE + 255) / 256, 256>>>(ei);
    k_scan_all<<<1, 1024>>>(ei);
    k_aggx<<<dim3(NN, 8), dim3(32, 4)>>>(x);
    k_pack<<<(GC * KCAT + 255) / 256, 256>>>(Wxr, Whr, Wxz, Whz, Wxn, Whn,
                                             bxr, bhr, bxz, bhz, bxn, bhn, Wfc);

    dim3 gateGrid(GC / BN, (ROWS + BM - 1) / BM);    // 16 x 157

    for (int t = 0; t < NT; t++) {
        if (t > 0) k_aggh<<<NN, dim3(64, 2)>>>();
        int K = (t == 0) ? NIN : KCAT;   // h=0 at t=0: skip h-side K entirely
        k_mma<true><<<gateGrid, 128>>>(pAxHi, pAxLo, pAhHi, pAhLo,
                                       pWThi, pWTlo, KCAT,
                                       nullptr, pbias, ROWS, K, t);
    }

    // one big FC GEMM over all timesteps: M=320000, K=256, N=128
    dim3 fcGrid(NOUT / BN, HISTROWS / BM);           // 2 x 2500
    k_mma<false><<<fcGrid, 128>>>(pHistHi, pHistLo, nullptr, nullptr,
                                  pWfcThi, pWfcTlo, NHID,
                                  out, bfc, HISTROWS, NHID, 0);
}

// round 14
// speedup vs baseline: 1.2107x; 1.2107x over previous
#include <cuda_runtime.h>
#include <cuda_bf16.h>
#include <cstdint>

// Problem constants (fixed shapes)
#define NB   2
#define NT   16
#define NN   10000
#define NIN  128
#define NHID 256
#define NOUT 128
#define NE   160000

#define ROWS (NB*NN)          // 20000
#define HISTROWS (NB*NT*NN)   // 320000
#define KCAT 384              // 128 (x-agg) + 256 (h-agg)
#define GC   1024             // interleaved: col 4*d+gate, gate = r,z,xn,hn

// GEMM tiles: 256 threads = 8 warps (2 M x 4 N), warp tile 64x32
#define BM 128
#define BN 128
#define BK 16
#define STAGE_BYTES 16384u    // Ahi4K|Alo4K|Bhi4K|Blo4K

typedef __nv_bfloat16 bf16;

// ---------------- device scratch (static, no allocations) ----------------
__device__ bf16  g_AxHi[(size_t)HISTROWS * NIN];    // 82 MB  (A*x_t, all t)
__device__ bf16  g_AxLo[(size_t)HISTROWS * NIN];
__device__ bf16  g_AhHi[(size_t)ROWS * NHID];       // 10.2 MB (A*h, current step)
__device__ bf16  g_AhLo[(size_t)ROWS * NHID];
__device__ float g_h[(size_t)ROWS * NHID];          // 20.5 MB (fp32 h state)
__device__ bf16  g_histHi[(size_t)HISTROWS * NHID]; // 164 MB (h_t splits, all t)
__device__ bf16  g_histLo[(size_t)HISTROWS * NHID];
__device__ bf16  g_WThi[GC * KCAT];                 // [n'][k] transposed
__device__ bf16  g_WTlo[GC * KCAT];
__device__ bf16  g_WfcThi[NOUT * NHID];             // [o][k]
__device__ bf16  g_WfcTlo[NOUT * NHID];
__device__ float g_biasPack[GC];                    // interleaved 4*d+gate
__device__ int   g_rowptr[NN + 1];
__device__ int   g_counts[NN];
__device__ int   g_fill[NN];
__device__ float g_dinv[NN];
__device__ int   g_col[NE];
__device__ float g_wedge[NE];

__device__ __forceinline__ void split2(float v, bf16& hi, bf16& lo) {
    hi = __float2bfloat16_rn(v);
    lo = __float2bfloat16_rn(v - __bfloat162float(hi));
}

// ---------------- setup kernels ----------------
__global__ void k_zero_all() {
    for (int i = blockIdx.x * blockDim.x + threadIdx.x;
         i < ROWS * NHID; i += gridDim.x * blockDim.x) {
        if (i < NN) g_counts[i] = 0;
        g_h[i] = 0.0f;
    }
}

__global__ void k_count(const int* __restrict__ ei) {
    int e = blockIdx.x * blockDim.x + threadIdx.x;
    if (e < NE) atomicAdd(&g_counts[ei[NE + e]], 1);   // dst row
}

// single block: dinv + exclusive scan + fill init + CSR scatter
__global__ void k_scan_all(const int* __restrict__ ei) {
    __shared__ int ssum[1024];
    int tid = threadIdx.x;
    const int CH = (NN + 1023) / 1024;   // 10
    int start = tid * CH;
    int s = 0;
    for (int i = 0; i < CH; i++) {
        int idx = start + i;
        if (idx < NN) s += g_counts[idx];
    }
    ssum[tid] = s;
    __syncthreads();
    for (int off = 1; off < 1024; off <<= 1) {
        int v = 0;
        if (tid >= off) v = ssum[tid - off];
        __syncthreads();
        ssum[tid] += v;
        __syncthreads();
    }
    int run = ssum[tid] - s;   // exclusive prefix
    for (int i = 0; i < CH; i++) {
        int idx = start + i;
        if (idx < NN) {
            g_rowptr[idx] = run;
            g_fill[idx]   = run;
            g_dinv[idx]   = rsqrtf((float)g_counts[idx] + 1.0f);
            run += g_counts[idx];
        }
    }
    if (tid == 1023) g_rowptr[NN] = ssum[1023];
    __syncthreads();
    for (int e = tid; e < NE; e += 1024) {
        int sc = ei[e];
        int d  = ei[NE + e];
        int pos = atomicAdd(&g_fill[d], 1);
        g_col[pos]   = sc;
        g_wedge[pos] = g_dinv[sc] * g_dinv[d];
    }
}

// ---------------- agg(x_t) for ALL t in one launch ----------------
__global__ void k_aggx(const float* __restrict__ x) {
    int node = blockIdx.x;
    int bt = blockIdx.y * 4 + threadIdx.y;   // 0..31, = t*NB + b
    int t = bt >> 1, b = bt & 1;
    int tx = threadIdx.x;                    // feature/4
    const float* vi = x + ((size_t)(b * NT + t) * NN) * NIN;
    float di = g_dinv[node];
    float4 acc = *(const float4*)(vi + (size_t)node * NIN + tx * 4);
    float sw = di * di;
    acc.x *= sw; acc.y *= sw; acc.z *= sw; acc.w *= sw;
    int beg = g_rowptr[node], end = g_rowptr[node + 1];
    int j = beg;
    for (; j + 1 < end; j += 2) {
        float w0 = g_wedge[j],     w1 = g_wedge[j + 1];
        int   c0 = g_col[j],       c1 = g_col[j + 1];
        float4 v0 = *(const float4*)(vi + (size_t)c0 * NIN + tx * 4);
        float4 v1 = *(const float4*)(vi + (size_t)c1 * NIN + tx * 4);
        acc.x += w0 * v0.x + w1 * v1.x; acc.y += w0 * v0.y + w1 * v1.y;
        acc.z += w0 * v0.z + w1 * v1.z; acc.w += w0 * v0.w + w1 * v1.w;
    }
    if (j < end) {
        float w = g_wedge[j]; int c = g_col[j];
        float4 v = *(const float4*)(vi + (size_t)c * NIN + tx * 4);
        acc.x += w * v.x; acc.y += w * v.y; acc.z += w * v.z; acc.w += w * v.w;
    }
    size_t o = ((size_t)bt * NN + node) * NIN + tx * 4;  // = (t*ROWS + b*NN + node)*NIN
    bf16 h0, l0, h1, l1, h2, l2, h3, l3;
    split2(acc.x, h0, l0); split2(acc.y, h1, l1);
    split2(acc.z, h2, l2); split2(acc.w, h3, l3);
    *(ushort4*)(g_AxHi + o) = make_ushort4(__bfloat16_as_ushort(h0), __bfloat16_as_ushort(h1),
                                           __bfloat16_as_ushort(h2), __bfloat16_as_ushort(h3));
    *(ushort4*)(g_AxLo + o) = make_ushort4(__bfloat16_as_ushort(l0), __bfloat16_as_ushort(l1),
                                           __bfloat16_as_ushort(l2), __bfloat16_as_ushort(l3));
}

// ---------------- agg(h) per step ----------------
__global__ void k_aggh() {
    int node = blockIdx.x;
    int b    = threadIdx.y;
    int tx   = threadIdx.x;          // 0..63
    const float* vi = g_h + (size_t)b * NN * NHID;
    float di = g_dinv[node];
    float4 acc = *(const float4*)(vi + (size_t)node * NHID + tx * 4);
    float sw = di * di;
    acc.x *= sw; acc.y *= sw; acc.z *= sw; acc.w *= sw;
    int beg = g_rowptr[node], end = g_rowptr[node + 1];
    int j = beg;
    for (; j + 1 < end; j += 2) {
        float w0 = g_wedge[j],     w1 = g_wedge[j + 1];
        int   c0 = g_col[j],       c1 = g_col[j + 1];
        float4 v0 = *(const float4*)(vi + (size_t)c0 * NHID + tx * 4);
        float4 v1 = *(const float4*)(vi + (size_t)c1 * NHID + tx * 4);
        acc.x += w0 * v0.x + w1 * v1.x; acc.y += w0 * v0.y + w1 * v1.y;
        acc.z += w0 * v0.z + w1 * v1.z; acc.w += w0 * v0.w + w1 * v1.w;
    }
    if (j < end) {
        float w = g_wedge[j]; int c = g_col[j];
        float4 v = *(const float4*)(vi + (size_t)c * NHID + tx * 4);
        acc.x += w * v.x; acc.y += w * v.y; acc.z += w * v.z; acc.w += w * v.w;
    }
    size_t o = ((size_t)b * NN + node) * NHID + tx * 4;
    bf16 h0, l0, h1, l1, h2, l2, h3, l3;
    split2(acc.x, h0, l0); split2(acc.y, h1, l1);
    split2(acc.z, h2, l2); split2(acc.w, h3, l3);
    *(ushort4*)(g_AhHi + o) = make_ushort4(__bfloat16_as_ushort(h0), __bfloat16_as_ushort(h1),
                                           __bfloat16_as_ushort(h2), __bfloat16_as_ushort(h3));
    *(ushort4*)(g_AhLo + o) = make_ushort4(__bfloat16_as_ushort(l0), __bfloat16_as_ushort(l1),
                                           __bfloat16_as_ushort(l2), __bfloat16_as_ushort(l3));
}

// ---------------- weight packing (transposed + gate-interleaved + split) ----
__global__ void k_pack(const float* __restrict__ Wxr, const float* __restrict__ Whr,
                       const float* __restrict__ Wxz, const float* __restrict__ Whz,
                       const float* __restrict__ Wxn, const float* __restrict__ Whn,
                       const float* __restrict__ bxr, const float* __restrict__ bhr,
                       const float* __restrict__ bxz, const float* __restrict__ bhz,
                       const float* __restrict__ bxn, const float* __restrict__ bhn,
                       const float* __restrict__ Wfc) {
    int idx = blockIdx.x * blockDim.x + threadIdx.x;
    if (idx < GC * KCAT) {
        int cp = idx / KCAT;
        int k  = idx - cp * KCAT;
        int d = cp >> 2, g = cp & 3;
        bool xk = k < 128;
        int kh = k - 128;
        float v;
        if (g == 0)      v = xk ? Wxr[k * 256 + d] : Whr[kh * 256 + d];
        else if (g == 1) v = xk ? Wxz[k * 256 + d] : Whz[kh * 256 + d];
        else if (g == 2) v = xk ? Wxn[k * 256 + d] : 0.0f;
        else             v = xk ? 0.0f : Whn[kh * 256 + d];
        bf16 hi, lo; split2(v, hi, lo);
        g_WThi[idx] = hi; g_WTlo[idx] = lo;
    }
    if (idx < GC) {
        int d = idx >> 2, g = idx & 3;
        float bv;
        if (g == 0)      bv = bxr[d] + bhr[d];
        else if (g == 1) bv = bxz[d] + bhz[d];
        else if (g == 2) bv = bxn[d];
        else             bv = bhn[d];
        g_biasPack[idx] = bv;
    }
    if (idx < NOUT * NHID) {
        int o = idx >> 8;          // NHID = 256
        int k = idx & 255;
        bf16 hi, lo; split2(Wfc[k * NOUT + o], hi, lo);
        g_WfcThi[idx] = hi; g_WfcTlo[idx] = lo;
    }
}

// ---------------- split-bf16 mma.sync GEMM (3-stage, 2 CTAs/SM) ----------
// GATES=true: A = [Ax(t) | Ah], K=384 (128 at t=0); fused GRU epilogue
//             updating g_h + writing h splits into hist[t].
// GATES=false: A = hist (M=320000, K=256); bias + scatter into out[B,T,N,OUT].

__device__ __forceinline__ uint32_t smem_u32(const void* p) {
    uint32_t a;
    asm("{ .reg .u64 t; cvta.to.shared.u64 t, %1; cvt.u32.u64 %0, t; }"
        : "=r"(a) : "l"(p));
    return a;
}

__device__ __forceinline__ void ldsm4(uint32_t& r0, uint32_t& r1, uint32_t& r2,
                                      uint32_t& r3, uint32_t addr) {
    asm volatile("ldmatrix.sync.aligned.m8n8.x4.shared.b16 {%0,%1,%2,%3}, [%4];"
                 : "=r"(r0), "=r"(r1), "=r"(r2), "=r"(r3) : "r"(addr));
}

__device__ __forceinline__ void mma16(float* c, const uint32_t* a, const uint32_t* b) {
    asm volatile(
        "mma.sync.aligned.m16n8k16.row.col.f32.bf16.bf16.f32 "
        "{%0,%1,%2,%3}, {%4,%5,%6,%7}, {%8,%9}, {%0,%1,%2,%3};"
        : "+f"(c[0]), "+f"(c[1]), "+f"(c[2]), "+f"(c[3])
        : "r"(a[0]), "r"(a[1]), "r"(a[2]), "r"(a[3]), "r"(b[0]), "r"(b[1]));
}

template <bool GATES>
__global__ void __launch_bounds__(256, 2)
k_mma(const bf16* __restrict__ A0hi, const bf16* __restrict__ A0lo,
      const bf16* __restrict__ A1hi, const bf16* __restrict__ A1lo,
      const bf16* __restrict__ Bhi, const bf16* __restrict__ Blo, int ldb,
      float* __restrict__ C, const float* __restrict__ bias,
      int M, int K, int t) {
    // 3 stages x 16KB: [Ahi 4K: kh*2048+row*16][Alo 4K][Bhi 4K][Blo 4K]
    __shared__ __align__(16) char smem[3 * STAGE_BYTES];

    const int tid = threadIdx.x;
    const int lane = tid & 31;
    const int wid = tid >> 5;
    const int wm = wid & 1;          // 2 warps in M
    const int wn = wid >> 1;         // 4 warps in N
    const int m0 = blockIdx.y * BM;
    const int n0 = blockIdx.x * BN;

    const uint32_t sbase = smem_u32(smem);
    const int st_row = tid >> 1;
    const int st_kh  = tid & 1;

    const int r = m0 + st_row;
    const bool rvalid = r < M;
    const int rc = rvalid ? r : 0;
    const bf16 *aXhi, *aXlo, *aHhi, *aHlo;
    if (GATES) {
        size_t xoff = ((size_t)t * ROWS + rc) * NIN + st_kh * 8;
        aXhi = A0hi + xoff; aXlo = A0lo + xoff;
        size_t hoff = (size_t)rc * NHID + st_kh * 8;
        aHhi = A1hi + hoff; aHlo = A1lo + hoff;
    } else {
        size_t off = (size_t)rc * NHID + st_kh * 8;
        aXhi = A0hi + off; aXlo = A0lo + off;
        aHhi = A0hi; aHlo = A0lo;   // unused
    }
    const bf16* bSrcHi = Bhi + (size_t)(n0 + st_row) * ldb + st_kh * 8;
    const bf16* bSrcLo = Blo + (size_t)(n0 + st_row) * ldb + st_kh * 8;
    const int pa = rvalid ? 16 : 0;

    // ldmatrix lane geometry (same formula for A and B)
    const int lrow = lane & 15;
    const int lkh  = lane >> 4;

    float acc[4][4][4];
#pragma unroll
    for (int i = 0; i < 4; i++)
#pragma unroll
        for (int j = 0; j < 4; j++)
#pragma unroll
            for (int q = 0; q < 4; q++) acc[i][j][q] = 0.0f;

    const int KT = K / BK;

    auto stage = [&](int buf, int k0) {
        uint32_t base = sbase + (uint32_t)buf * STAGE_BYTES;
        uint32_t o = (uint32_t)(st_kh * 2048 + st_row * 16);
        const bf16 *sa_hi, *sa_lo;
        if (GATES && k0 >= NIN) { sa_hi = aHhi + (k0 - NIN); sa_lo = aHlo + (k0 - NIN); }
        else                    { sa_hi = aXhi + k0;         sa_lo = aXlo + k0; }
        asm volatile("cp.async.ca.shared.global [%0], [%1], 16, %2;"
                     :: "r"(base + o), "l"(sa_hi), "r"(pa));
        asm volatile("cp.async.ca.shared.global [%0], [%1], 16, %2;"
                     :: "r"(base + 4096u + o), "l"(sa_lo), "r"(pa));
        asm volatile("cp.async.ca.shared.global [%0], [%1], 16, %2;"
                     :: "r"(base + 8192u + o), "l"(bSrcHi + k0), "r"(16));
        asm volatile("cp.async.ca.shared.global [%0], [%1], 16, %2;"
                     :: "r"(base + 12288u + o), "l"(bSrcLo + k0), "r"(16));
    };

    stage(0, 0);
    asm volatile("cp.async.commit_group;");
    stage(1, BK);
    asm volatile("cp.async.commit_group;");

    for (int kt = 0; kt < KT; kt++) {
        if (kt + 2 < KT) {
            stage((kt + 2) % 3, (kt + 2) * BK);
            asm volatile("cp.async.commit_group;");
            asm volatile("cp.async.wait_group 2;");
        } else if (kt + 1 < KT) {
            asm volatile("cp.async.wait_group 1;");
        } else {
            asm volatile("cp.async.wait_group 0;");
        }
        __syncthreads();

        const uint32_t pA  = sbase + (uint32_t)(kt % 3) * STAGE_BYTES;
        const uint32_t pA2 = pA + 4096u;
        const uint32_t pB  = pA + 8192u;
        const uint32_t pB2 = pA + 12288u;
        const uint32_t loff = (uint32_t)(lkh * 2048);

        // B fragments held across the iteration (16 regs)
        uint32_t bh[4][2], bl[4][2];
#pragma unroll
        for (int j = 0; j < 2; j++) {
            uint32_t ro = (uint32_t)((wn * 32 + j * 16 + lrow) * 16);
            uint32_t r0, r1, r2, r3;
            ldsm4(r0, r1, r2, r3, pB + loff + ro);
            bh[2*j][0] = r0; bh[2*j][1] = r2;
            bh[2*j+1][0] = r1; bh[2*j+1][1] = r3;
            ldsm4(r0, r1, r2, r3, pB2 + loff + ro);
            bl[2*j][0] = r0; bl[2*j][1] = r2;
            bl[2*j+1][0] = r1; bl[2*j+1][1] = r3;
        }
        // A fragments in 2 groups of 2 mt-tiles (16 live regs instead of 32)
#pragma unroll
        for (int mtg = 0; mtg < 2; mtg++) {
            uint32_t ah[2][4], al[2][4];
#pragma unroll
            for (int mi = 0; mi < 2; mi++) {
                int mt = mtg * 2 + mi;
                uint32_t ro = (uint32_t)((wm * 64 + mt * 16 + lrow) * 16);
                ldsm4(ah[mi][0], ah[mi][1], ah[mi][2], ah[mi][3], pA + loff + ro);
                ldsm4(al[mi][0], al[mi][1], al[mi][2], al[mi][3], pA2 + loff + ro);
            }
#pragma unroll
            for (int mi = 0; mi < 2; mi++)
#pragma unroll
                for (int nt = 0; nt < 4; nt++) {
                    float* a4 = acc[mtg * 2 + mi][nt];
                    mma16(a4, ah[mi], bh[nt]);
                    mma16(a4, ah[mi], bl[nt]);
                    mma16(a4, al[mi], bh[nt]);
                }
        }
        __syncthreads();
    }

    // ---- epilogue ----
    const int gid = lane >> 2, tg = lane & 3;

    if (GATES) {
        const bool odd = lane & 1;
#pragma unroll
        for (int mt = 0; mt < 4; mt++) {
            int rowb = m0 + wm * 64 + mt * 16;
#pragma unroll
            for (int nt = 0; nt < 4; nt++) {
                float c0 = acc[mt][nt][0], c1 = acc[mt][nt][1];
                float c2 = acc[mt][nt][2], c3 = acc[mt][nt][3];
                float e0 = __shfl_xor_sync(0xffffffffu, c0, 1);
                float e1 = __shfl_xor_sync(0xffffffffu, c1, 1);
                float e2 = __shfl_xor_sync(0xffffffffu, c2, 1);
                float e3 = __shfl_xor_sync(0xffffffffu, c3, 1);
                float v0, v1, v2, v3;
                int row;
                if (!odd) { v0 = c0; v1 = c1; v2 = e0; v3 = e1; row = rowb + gid; }
                else      { v0 = e2; v1 = e3; v2 = c2; v3 = c3; row = rowb + gid + 8; }
                int d = ((n0 + wn * 32 + nt * 8) >> 2) + (tg >> 1);
                if (row < M) {
                    float4 bb = *(const float4*)&bias[4 * d];
                    float rg = 1.0f / (1.0f + __expf(-(v0 + bb.x)));
                    float zg = 1.0f / (1.0f + __expf(-(v1 + bb.y)));
                    float ng = tanhf(v2 + bb.z + rg * (v3 + bb.w));
                    size_t hoff = (size_t)row * NHID + d;
                    float h = g_h[hoff];
                    float hn2 = h + zg * (ng - h);
                    g_h[hoff] = hn2;
                    bf16 hi, lo; split2(hn2, hi, lo);
                    size_t hist = ((size_t)t * ROWS + row) * NHID + d;
                    g_histHi[hist] = hi;
                    g_histLo[hist] = lo;
                }
            }
        }
    } else {
#pragma unroll
        for (int mt = 0; mt < 4; mt++) {
            int r0 = m0 + wm * 64 + mt * 16 + gid;
            int r1 = r0 + 8;
            // r = t*ROWS + b*NN + node -> out[((b*NT+t)*NN+node)*NOUT]
            int t0 = r0 / ROWS, rm0 = r0 - t0 * ROWS;
            int b0 = rm0 / NN,  nd0 = rm0 - b0 * NN;
            int t1 = r1 / ROWS, rm1 = r1 - t1 * ROWS;
            int b1 = rm1 / NN,  nd1 = rm1 - b1 * NN;
            size_t base0 = (((size_t)b0 * NT + t0) * NN + nd0) * NOUT;
            size_t base1 = (((size_t)b1 * NT + t1) * NN + nd1) * NOUT;
#pragma unroll
            for (int nt = 0; nt < 4; nt++) {
                int col = n0 + wn * 32 + nt * 8 + tg * 2;
                float bx = bias[col], by = bias[col + 1];
                float2 o0 = make_float2(acc[mt][nt][0] + bx, acc[mt][nt][1] + by);
                *(float2*)&C[base0 + col] = o0;
                float2 o1 = make_float2(acc[mt][nt][2] + bx, acc[mt][nt][3] + by);
                *(float2*)&C[base1 + col] = o1;
            }
        }
    }
}

// ---------------- launcher ----------------
extern "C" void kernel_launch(void* const* d_in, const int* in_sizes, int n_in,
                              void* d_out, int out_size) {
    (void)in_sizes; (void)n_in; (void)out_size;
    const float* x   = (const float*)d_in[0];
    const int*   ei  = (const int*)d_in[1];
    const float* Wxr = (const float*)d_in[2];  const float* bxr = (const float*)d_in[3];
    const float* Whr = (const float*)d_in[4];  const float* bhr = (const float*)d_in[5];
    const float* Wxz = (const float*)d_in[6];  const float* bxz = (const float*)d_in[7];
    const float* Whz = (const float*)d_in[8];  const float* bhz = (const float*)d_in[9];
    const float* Wxn = (const float*)d_in[10]; const float* bxn = (const float*)d_in[11];
    const float* Whn = (const float*)d_in[12]; const float* bhn = (const float*)d_in[13];
    const float* Wfc = (const float*)d_in[14]; const float* bfc = (const float*)d_in[15];
    float* out = (float*)d_out;

    bf16 *pAxHi, *pAxLo, *pAhHi, *pAhLo, *pHistHi, *pHistLo;
    bf16 *pWThi, *pWTlo, *pWfcThi, *pWfcTlo;
    float *pbias;
    cudaGetSymbolAddress((void**)&pAxHi,   g_AxHi);
    cudaGetSymbolAddress((void**)&pAxLo,   g_AxLo);
    cudaGetSymbolAddress((void**)&pAhHi,   g_AhHi);
    cudaGetSymbolAddress((void**)&pAhLo,   g_AhLo);
    cudaGetSymbolAddress((void**)&pHistHi, g_histHi);
    cudaGetSymbolAddress((void**)&pHistLo, g_histLo);
    cudaGetSymbolAddress((void**)&pWThi,   g_WThi);
    cudaGetSymbolAddress((void**)&pWTlo,   g_WTlo);
    cudaGetSymbolAddress((void**)&pWfcThi, g_WfcThi);
    cudaGetSymbolAddress((void**)&pWfcTlo, g_WfcTlo);
    cudaGetSymbolAddress((void**)&pbias,   g_biasPack);

    // setup
    k_zero_all<<<592, 256>>>();
    k_count<<<(NE + 255) / 256, 256>>>(ei);
    k_scan_all<<<1, 1024>>>(ei);
    k_aggx<<<dim3(NN, 8), dim3(32, 4)>>>(x);
    k_pack<<<(GC * KCAT + 255) / 256, 256>>>(Wxr, Whr, Wxz, Whz, Wxn, Whn,
                                             bxr, bhr, bxz, bhz, bxn, bhn, Wfc);

    dim3 gateGrid(GC / BN, (ROWS + BM - 1) / BM);    // 8 x 157

    for (int t = 0; t < NT; t++) {
        if (t > 0) k_aggh<<<NN, dim3(64, 2)>>>();
        int K = (t == 0) ? NIN : KCAT;   // h=0 at t=0: skip h-side K entirely
        k_mma<true><<<gateGrid, 256>>>(pAxHi, pAxLo, pAhHi, pAhLo,
                                       pWThi, pWTlo, KCAT,
                                       nullptr, pbias, ROWS, K, t);
    }

    // one big FC GEMM over all timesteps: M=320000, K=256, N=128
    dim3 fcGrid(NOUT / BN, HISTROWS / BM);           // 1 x 2500
    k_mma<false><<<fcGrid, 256>>>(pHistHi, pHistLo, nullptr, nullptr,
                                  pWfcThi, pWfcTlo, NHID,
                                  out, bfc, HISTROWS, NHID, 0);
}